// round 7
// baseline (speedup 1.0000x reference)
#include <cuda_runtime.h>
#include <cuda_bf16.h>
#include <cstdint>

#define NN   256
#define CC   3
#define TT   300
#define VV   25
#define MM   2
#define DD   256
#define KK   5
#define TOPK 64
#define LTOT (NN*MM*TT)      // 153600
#define RPS  (MM*TT)         // 600
#define OUTS (CC*TOPK*VV*MM) // 9600 per sample
#define RPB  128             // rows per block (both passes)
#define NBLK (LTOT/RPB)      // 1200 blocks
#define EPSV 1e-8f

// -------- scratch (statically zero-initialized; re-zeroed by k_sel tail) --------
__device__ float g_cls_sum[KK * DD];
__device__ float g_cnt[KK];
__device__ float g_cm[KK * DD];
__device__ float g_inter[KK];
__device__ float g_Sb;
__device__ float g_Sw;
__device__ float g_fs[LTOT];

// -------- kernel 1: per-class sums + counts --------
// 1200 blocks x 256 threads, 128 rows/block. Thread = (slice s = tid>>6, colgroup c = tid&63).
// Rows: base + s + 4*it, it = 0..31. Label uniform per warp -> uniform branch.
__global__ void __launch_bounds__(256, 6) k_stats(const float4* __restrict__ xT4,
                                                  const int* __restrict__ labels) {
    __shared__ int    s_lbl[RPB];
    __shared__ float  s_cnt[KK];
    __shared__ float4 s_part[4][KK][64];   // 20 KB
    int tid = threadIdx.x;
    int c = tid & 63;
    int s = tid >> 6;
    int base = blockIdx.x * RPB;
    if (tid < KK) s_cnt[tid] = 0.f;
    if (tid < RPB) s_lbl[tid] = labels[base + tid];
    __syncthreads();
    if (tid < RPB) atomicAdd(&s_cnt[s_lbl[tid]], 1.f);

    float4 a[KK];
#pragma unroll
    for (int k = 0; k < KK; k++) a[k] = make_float4(0.f, 0.f, 0.f, 0.f);

    const float4* p = xT4 + (size_t)(base + s) * 64 + c;
    for (int it = 0; it < 32; it += 4) {
        float4 v[4];
        int l[4];
#pragma unroll
        for (int u = 0; u < 4; u++) v[u] = __ldg(p + (size_t)(it + u) * 256);
#pragma unroll
        for (int u = 0; u < 4; u++) l[u] = s_lbl[(it + u) * 4 + s];
#pragma unroll
        for (int u = 0; u < 4; u++) {
            int lu = l[u];
            float4 vu = v[u];
            if      (lu == 0) { a[0].x += vu.x; a[0].y += vu.y; a[0].z += vu.z; a[0].w += vu.w; }
            else if (lu == 1) { a[1].x += vu.x; a[1].y += vu.y; a[1].z += vu.z; a[1].w += vu.w; }
            else if (lu == 2) { a[2].x += vu.x; a[2].y += vu.y; a[2].z += vu.z; a[2].w += vu.w; }
            else if (lu == 3) { a[3].x += vu.x; a[3].y += vu.y; a[3].z += vu.z; a[3].w += vu.w; }
            else              { a[4].x += vu.x; a[4].y += vu.y; a[4].z += vu.z; a[4].w += vu.w; }
        }
    }
#pragma unroll
    for (int k = 0; k < KK; k++) s_part[s][k][c] = a[k];
    __syncthreads();

    for (int idx = tid; idx < KK * 64; idx += 256) {
        int k = idx >> 6, cc = idx & 63;
        float4 s0 = s_part[0][k][cc], s1 = s_part[1][k][cc];
        float4 s2 = s_part[2][k][cc], s3 = s_part[3][k][cc];
        float4 t;
        t.x = (s0.x + s1.x) + (s2.x + s3.x);
        t.y = (s0.y + s1.y) + (s2.y + s3.y);
        t.z = (s0.z + s1.z) + (s2.z + s3.z);
        t.w = (s0.w + s1.w) + (s2.w + s3.w);
        atomicAdd(&g_cls_sum[k * DD + cc * 4 + 0], t.x);
        atomicAdd(&g_cls_sum[k * DD + cc * 4 + 1], t.y);
        atomicAdd(&g_cls_sum[k * DD + cc * 4 + 2], t.z);
        atomicAdd(&g_cls_sum[k * DD + cc * 4 + 3], t.w);
    }
    if (tid < KK) atomicAdd(&g_cnt[tid], s_cnt[tid]);
}

// -------- kernel 2: means, inter, Sb (1 block) --------
__global__ void __launch_bounds__(256) k_finalize() {
    __shared__ float s_cnt[KK];
    __shared__ float red[256];
    int d = threadIdx.x;
    if (d < KK) s_cnt[d] = g_cnt[d];
    __syncthreads();

    float om = 0.f;
    float cm[KK];
#pragma unroll
    for (int k = 0; k < KK; k++) {
        float s = g_cls_sum[k * DD + d];
        om += s;
        cm[k] = s / fmaxf(s_cnt[k], 1.f);
        g_cm[k * DD + d] = cm[k];
    }
    om *= (1.0f / (float)LTOT);

#pragma unroll
    for (int k = 0; k < KK; k++) {
        float diff = cm[k] - om;
        red[d] = diff * diff;
        __syncthreads();
        for (int s = 128; s > 0; s >>= 1) {
            if (d < s) red[d] += red[d + s];
            __syncthreads();
        }
        if (d == 0) g_inter[k] = red[0];
        __syncthreads();
    }
    if (d == 0) {
        float sb = 0.f;
#pragma unroll
        for (int k = 0; k < KK; k++) sb += s_cnt[k] * g_inter[k];
        g_Sb = sb;
    }
}

// -------- kernel 3: intra + frame scores -> g_fs, Sw --------
// 1200 blocks x 256 threads = 8 warps; warp handles 16 rows, staged 4 rows (8 LDG.128 in flight).
__global__ void __launch_bounds__(256, 6) k_intra(const float4* __restrict__ xT4,
                                                  const int* __restrict__ labels) {
    __shared__ float s_cm[KK * DD];   // 5 KB
    __shared__ float s_inter[KK];
    __shared__ int   s_lbl[RPB];
    __shared__ float s_fs[RPB];
    __shared__ float s_sw[8];

    int tid = threadIdx.x, lane = tid & 31, w = tid >> 5;
    int base = (NBLK - 1 - (int)blockIdx.x) * RPB;   // reversed: L2-hot tail first

    for (int i = tid; i < KK * DD; i += 256) s_cm[i] = g_cm[i];
    if (tid < KK) s_inter[tid] = g_inter[tid];
    if (tid < RPB) s_lbl[tid] = labels[base + tid];
    __syncthreads();

    const float4* cm4 = (const float4*)s_cm;
    float swacc = 0.f;
    int r0 = w * 16;

    for (int rr = 0; rr < 16; rr += 4) {
        int r = r0 + rr;
        float4 xv[8];
#pragma unroll
        for (int u = 0; u < 4; u++) {
            const float4* p = xT4 + (size_t)(base + r + u) * 64;
            xv[2 * u]     = __ldg(p + lane);
            xv[2 * u + 1] = __ldg(p + lane + 32);
        }
        float acc[4];
#pragma unroll
        for (int u = 0; u < 4; u++) {
            int lbl = s_lbl[r + u];
            const float4* m = cm4 + lbl * 64;
            float4 m0 = m[lane], m1 = m[lane + 32];
            float4 x0 = xv[2 * u], x1 = xv[2 * u + 1];
            float a = 0.f;
            float d0 = x0.x - m0.x; a = fmaf(d0, d0, a);
            float d1 = x0.y - m0.y; a = fmaf(d1, d1, a);
            float d2 = x0.z - m0.z; a = fmaf(d2, d2, a);
            float d3 = x0.w - m0.w; a = fmaf(d3, d3, a);
            float d4 = x1.x - m1.x; a = fmaf(d4, d4, a);
            float d5 = x1.y - m1.y; a = fmaf(d5, d5, a);
            float d6 = x1.z - m1.z; a = fmaf(d6, d6, a);
            float d7 = x1.w - m1.w; a = fmaf(d7, d7, a);
            acc[u] = a;
        }
#pragma unroll
        for (int u = 0; u < 4; u++) {
#pragma unroll
            for (int o = 16; o; o >>= 1) acc[u] += __shfl_xor_sync(0xFFFFFFFFu, acc[u], o);
        }
        if (lane == 0) {
#pragma unroll
            for (int u = 0; u < 4; u++) {
                swacc += acc[u];
                s_fs[r + u] = s_inter[s_lbl[r + u]] / (acc[u] + EPSV);
            }
        }
    }
    if (lane == 0) s_sw[w] = swacc;
    __syncthreads();
    if (tid == 0) {
        float s = 0.f;
#pragma unroll
        for (int i = 0; i < 8; i++) s += s_sw[i];
        atomicAdd(&g_Sw, s);
    }
    if (tid < RPB) g_fs[base + tid] = s_fs[tid];   // coalesced
}

// -------- kernel 4: VF, topk, gather, loss, and re-zero scratch --------
// grid (NN, CC): block (n,c) computes topk for sample n (redundant across c, cheap)
// and gathers its contiguous 3200-float output slice.
__global__ void __launch_bounds__(320) k_sel(const float* __restrict__ x,
                                             float* __restrict__ out) {
    __shared__ float s_v[TT];
    __shared__ int   s_flag[TT];
    __shared__ int   s_idx[TOPK];
    int n = blockIdx.x;
    int c = blockIdx.y;
    int tid = threadIdx.x;

    if (tid < TT)
        s_v[tid] = 0.5f * (g_fs[n * RPS + tid] + g_fs[n * RPS + TT + tid]);
    __syncthreads();

    if (tid < TT) {
        float mv = s_v[tid];
        int rank = 0;
        for (int j = 0; j < TT; j++) {
            float o = s_v[j];
            rank += (o > mv) || (o == mv && j < tid);
        }
        s_flag[tid] = (rank < TOPK) ? 1 : 0;
    }
    __syncthreads();
    if (tid < TT && s_flag[tid]) {
        int pos = 0;
        for (int j = 0; j < tid; j++) pos += s_flag[j];
        s_idx[pos] = tid;
    }
    __syncthreads();

    // gather this block's slice: out layout [N, C, TOPK, V, M]
    const float* xb = x + ((size_t)n * CC + c) * TT * (VV * MM);
    float* ob = out + 1 + ((size_t)n * CC + c) * (TOPK * VV * MM);
    for (int o = tid; o < TOPK * VV * MM; o += 320) {
        int j = o / (VV * MM);
        int vm = o - j * (VV * MM);
        int t = s_idx[j];
        ob[o] = __ldg(xb + (size_t)t * (VV * MM) + vm);
    }

    // block (0,0): write loss, then re-zero accumulators for next graph replay
    if (n == 0 && c == 0) {
        if (tid == 0) out[0] = g_Sw / (g_Sb + EPSV);
        __syncthreads();
        for (int i = tid; i < KK * DD; i += 320) g_cls_sum[i] = 0.f;
        if (tid < KK) g_cnt[tid] = 0.f;
        if (tid == 0) g_Sw = 0.f;
    }
}

extern "C" void kernel_launch(void* const* d_in, const int* in_sizes, int n_in,
                              void* d_out, int out_size) {
    const float*  x      = (const float*)d_in[0];
    const float4* xT4    = (const float4*)d_in[1];
    const int*    labels = (const int*)d_in[2];
    float* out = (float*)d_out;
    (void)in_sizes; (void)n_in; (void)out_size;

    k_stats<<<NBLK, 256>>>(xT4, labels);
    k_finalize<<<1, 256>>>();
    k_intra<<<NBLK, 256>>>(xT4, labels);
    dim3 selgrid(NN, CC);
    k_sel<<<selgrid, 320>>>(x, out);
}

// round 8
// speedup vs baseline: 1.0538x; 1.0538x over previous
#include <cuda_runtime.h>
#include <cuda_bf16.h>
#include <cstdint>

#define NN   256
#define CC   3
#define TT   300
#define VV   25
#define MM   2
#define DD   256
#define KK   5
#define TOPK 64
#define LTOT (NN*MM*TT)      // 153600
#define RPS  (MM*TT)         // 600
#define OUTS (CC*TOPK*VV*MM) // 9600 per sample
#define RPB  128             // rows per block (both passes)
#define NBLK (LTOT/RPB)      // 1200 blocks
#define EPSV 1e-8f

// -------- scratch (statically zero-initialized; re-zeroed by k_sel tail) --------
__device__ float g_cls_sum[KK * DD];
__device__ float g_cnt[KK];
__device__ float g_cm[KK * DD];
__device__ float g_inter[KK];
__device__ float g_Sb;
__device__ float g_Sw;
__device__ float g_fs[LTOT];

// -------- kernel 1: per-class sums + counts --------
__global__ void __launch_bounds__(256, 6) k_stats(const float4* __restrict__ xT4,
                                                  const int* __restrict__ labels) {
    __shared__ int    s_lbl[RPB];
    __shared__ float  s_cnt[KK];
    __shared__ float4 s_part[4][KK][64];   // 20 KB
    int tid = threadIdx.x;
    int c = tid & 63;
    int s = tid >> 6;
    int base = blockIdx.x * RPB;
    if (tid < KK) s_cnt[tid] = 0.f;
    if (tid < RPB) s_lbl[tid] = labels[base + tid];
    __syncthreads();
    if (tid < RPB) atomicAdd(&s_cnt[s_lbl[tid]], 1.f);

    float4 a[KK];
#pragma unroll
    for (int k = 0; k < KK; k++) a[k] = make_float4(0.f, 0.f, 0.f, 0.f);

    const float4* p = xT4 + (size_t)(base + s) * 64 + c;
    for (int it = 0; it < 32; it += 4) {
        float4 v[4];
        int l[4];
#pragma unroll
        for (int u = 0; u < 4; u++) v[u] = __ldg(p + (size_t)(it + u) * 256);
#pragma unroll
        for (int u = 0; u < 4; u++) l[u] = s_lbl[(it + u) * 4 + s];
#pragma unroll
        for (int u = 0; u < 4; u++) {
            int lu = l[u];
            float4 vu = v[u];
            if      (lu == 0) { a[0].x += vu.x; a[0].y += vu.y; a[0].z += vu.z; a[0].w += vu.w; }
            else if (lu == 1) { a[1].x += vu.x; a[1].y += vu.y; a[1].z += vu.z; a[1].w += vu.w; }
            else if (lu == 2) { a[2].x += vu.x; a[2].y += vu.y; a[2].z += vu.z; a[2].w += vu.w; }
            else if (lu == 3) { a[3].x += vu.x; a[3].y += vu.y; a[3].z += vu.z; a[3].w += vu.w; }
            else              { a[4].x += vu.x; a[4].y += vu.y; a[4].z += vu.z; a[4].w += vu.w; }
        }
    }
#pragma unroll
    for (int k = 0; k < KK; k++) s_part[s][k][c] = a[k];
    __syncthreads();

    for (int idx = tid; idx < KK * 64; idx += 256) {
        int k = idx >> 6, cc = idx & 63;
        float4 s0 = s_part[0][k][cc], s1 = s_part[1][k][cc];
        float4 s2 = s_part[2][k][cc], s3 = s_part[3][k][cc];
        float4 t;
        t.x = (s0.x + s1.x) + (s2.x + s3.x);
        t.y = (s0.y + s1.y) + (s2.y + s3.y);
        t.z = (s0.z + s1.z) + (s2.z + s3.z);
        t.w = (s0.w + s1.w) + (s2.w + s3.w);
        atomicAdd(&g_cls_sum[k * DD + cc * 4 + 0], t.x);
        atomicAdd(&g_cls_sum[k * DD + cc * 4 + 1], t.y);
        atomicAdd(&g_cls_sum[k * DD + cc * 4 + 2], t.z);
        atomicAdd(&g_cls_sum[k * DD + cc * 4 + 3], t.w);
    }
    if (tid < KK) atomicAdd(&g_cnt[tid], s_cnt[tid]);
}

// -------- kernel 2: means, inter, Sb (1 block) --------
__global__ void __launch_bounds__(256) k_finalize() {
    __shared__ float s_cnt[KK];
    __shared__ float red[256];
    int d = threadIdx.x;
    if (d < KK) s_cnt[d] = g_cnt[d];
    __syncthreads();

    float om = 0.f;
    float cm[KK];
#pragma unroll
    for (int k = 0; k < KK; k++) {
        float s = g_cls_sum[k * DD + d];
        om += s;
        cm[k] = s / fmaxf(s_cnt[k], 1.f);
        g_cm[k * DD + d] = cm[k];
    }
    om *= (1.0f / (float)LTOT);

#pragma unroll
    for (int k = 0; k < KK; k++) {
        float diff = cm[k] - om;
        red[d] = diff * diff;
        __syncthreads();
        for (int s = 128; s > 0; s >>= 1) {
            if (d < s) red[d] += red[d + s];
            __syncthreads();
        }
        if (d == 0) g_inter[k] = red[0];
        __syncthreads();
    }
    if (d == 0) {
        float sb = 0.f;
#pragma unroll
        for (int k = 0; k < KK; k++) sb += s_cnt[k] * g_inter[k];
        g_Sb = sb;
    }
}

// -------- kernel 3: intra + frame scores -> g_fs, Sw --------
__global__ void __launch_bounds__(256, 6) k_intra(const float4* __restrict__ xT4,
                                                  const int* __restrict__ labels) {
    __shared__ float s_cm[KK * DD];   // 5 KB
    __shared__ float s_inter[KK];
    __shared__ int   s_lbl[RPB];
    __shared__ float s_fs[RPB];
    __shared__ float s_sw[8];

    int tid = threadIdx.x, lane = tid & 31, w = tid >> 5;
    int base = (NBLK - 1 - (int)blockIdx.x) * RPB;   // reversed: L2-hot tail first

    for (int i = tid; i < KK * DD; i += 256) s_cm[i] = g_cm[i];
    if (tid < KK) s_inter[tid] = g_inter[tid];
    if (tid < RPB) s_lbl[tid] = labels[base + tid];
    __syncthreads();

    const float4* cm4 = (const float4*)s_cm;
    float swacc = 0.f;
    int r0 = w * 16;

    for (int rr = 0; rr < 16; rr += 4) {
        int r = r0 + rr;
        float4 xv[8];
#pragma unroll
        for (int u = 0; u < 4; u++) {
            const float4* p = xT4 + (size_t)(base + r + u) * 64;
            xv[2 * u]     = __ldg(p + lane);
            xv[2 * u + 1] = __ldg(p + lane + 32);
        }
        float acc[4];
#pragma unroll
        for (int u = 0; u < 4; u++) {
            int lbl = s_lbl[r + u];
            const float4* m = cm4 + lbl * 64;
            float4 m0 = m[lane], m1 = m[lane + 32];
            float4 x0 = xv[2 * u], x1 = xv[2 * u + 1];
            float a = 0.f;
            float d0 = x0.x - m0.x; a = fmaf(d0, d0, a);
            float d1 = x0.y - m0.y; a = fmaf(d1, d1, a);
            float d2 = x0.z - m0.z; a = fmaf(d2, d2, a);
            float d3 = x0.w - m0.w; a = fmaf(d3, d3, a);
            float d4 = x1.x - m1.x; a = fmaf(d4, d4, a);
            float d5 = x1.y - m1.y; a = fmaf(d5, d5, a);
            float d6 = x1.z - m1.z; a = fmaf(d6, d6, a);
            float d7 = x1.w - m1.w; a = fmaf(d7, d7, a);
            acc[u] = a;
        }
#pragma unroll
        for (int u = 0; u < 4; u++) {
#pragma unroll
            for (int o = 16; o; o >>= 1) acc[u] += __shfl_xor_sync(0xFFFFFFFFu, acc[u], o);
        }
        if (lane == 0) {
#pragma unroll
            for (int u = 0; u < 4; u++) {
                swacc += acc[u];
                s_fs[r + u] = s_inter[s_lbl[r + u]] / (acc[u] + EPSV);
            }
        }
    }
    if (lane == 0) s_sw[w] = swacc;
    __syncthreads();
    if (tid == 0) {
        float s = 0.f;
#pragma unroll
        for (int i = 0; i < 8; i++) s += s_sw[i];
        atomicAdd(&g_Sw, s);
    }
    if (tid < RPB) g_fs[base + tid] = s_fs[tid];   // coalesced
}

// -------- kernel 4: VF, topk (once per sample), gather all 3 channels, loss, re-zero --------
// 256 blocks x 512 threads.
__global__ void __launch_bounds__(512) k_sel(const float* __restrict__ x,
                                             float* __restrict__ out) {
    __shared__ float s_v[TT];
    __shared__ int   s_flag[TT];
    __shared__ int   s_idx[TOPK];
    int n = blockIdx.x;
    int tid = threadIdx.x;

    if (tid < TT)
        s_v[tid] = 0.5f * (g_fs[n * RPS + tid] + g_fs[n * RPS + TT + tid]);
    __syncthreads();

    if (tid < TT) {
        float mv = s_v[tid];
        int rank = 0;
        for (int j = 0; j < TT; j++) {
            float o = s_v[j];
            rank += (o > mv) || (o == mv && j < tid);
        }
        s_flag[tid] = (rank < TOPK) ? 1 : 0;
    }
    __syncthreads();
    if (tid < TT && s_flag[tid]) {
        int pos = 0;
        for (int j = 0; j < tid; j++) pos += s_flag[j];
        s_idx[pos] = tid;
    }
    __syncthreads();

    // gather: out layout [N, C, TOPK, V, M]; per sample 3 channels x 64 frames x 50
    const float* xb = x + (size_t)n * CC * TT * (VV * MM);
    float* ob = out + 1 + (size_t)n * OUTS;
    for (int o = tid; o < OUTS; o += 512) {
        int cj = o / (VV * MM);          // c*64 + j
        int vm = o - cj * (VV * MM);
        int j = cj & 63;
        int c = cj >> 6;
        int t = s_idx[j];
        ob[o] = __ldg(xb + ((size_t)c * TT + t) * (VV * MM) + vm);
    }

    // block 0: loss + re-zero accumulators for next graph replay
    if (n == 0) {
        if (tid == 0) out[0] = g_Sw / (g_Sb + EPSV);
        __syncthreads();
        for (int i = tid; i < KK * DD; i += 512) g_cls_sum[i] = 0.f;
        if (tid < KK) g_cnt[tid] = 0.f;
        if (tid == 0) g_Sw = 0.f;
    }
}

extern "C" void kernel_launch(void* const* d_in, const int* in_sizes, int n_in,
                              void* d_out, int out_size) {
    const float*  x      = (const float*)d_in[0];
    const float4* xT4    = (const float4*)d_in[1];
    const int*    labels = (const int*)d_in[2];
    float* out = (float*)d_out;
    (void)in_sizes; (void)n_in; (void)out_size;

    k_stats<<<NBLK, 256>>>(xT4, labels);
    k_finalize<<<1, 256>>>();
    k_intra<<<NBLK, 256>>>(xT4, labels);
    k_sel<<<NN, 512>>>(x, out);
}